// round 5
// baseline (speedup 1.0000x reference)
#include <cuda_runtime.h>
#include <cuda_bf16.h>

#define NPTS 1048576
#define KNEI 16
#define NTASKS (2 * NPTS)          // 2 tasks per point, 8 nbrs each
#define GRID_MAIN 888              // 148 SMs x 6 CTAs (forced by launch_bounds)
#define NTHREADS 256

// Padded points: 16B rows -> each random gather = exactly one 128B-line
// L1tex wavefront. Accumulator + tickets + grid barrier state.
__device__ float4 g_pts4[NPTS];
__device__ double g_acc;
__device__ unsigned int g_ticket;
__device__ unsigned int g_bar_count;   // arrivals this replay (reset by releaser)
__device__ unsigned int g_bar_phase;   // monotonic; flips release each replay

// Single fused persistent kernel:
//  phase 1: pad [N,3] f32 -> [N] float4 (grid-cooperative), reset acc/ticket
//  barrier: device-side, phase-based (safe across graph replays)
//  phase 2: grid-stride gather/accumulate + fused finalize
__global__ void __launch_bounds__(NTHREADS, 6) neighbour_loss_fused(
    const float* __restrict__ pts,
    const int*   __restrict__ idx,
    const float* __restrict__ orig,
    float*       __restrict__ out)
{
    const int tid  = threadIdx.x;
    const int gtid = blockIdx.x * NTHREADS + tid;
    const int gstride = GRID_MAIN * NTHREADS;

    // ---- phase 0: reset per-replay scalars (block 0, before barrier) ----
    if (gtid == 0) { g_acc = 0.0; g_ticket = 0u; }

    // ---- phase 1: pad points (4 points per loop iteration per thread) ----
    for (int i = gtid; i < NPTS / 4; i += gstride) {
        const float4* p4 = reinterpret_cast<const float4*>(pts) + 3 * i;
        float4 a = p4[0];
        float4 b = p4[1];
        float4 c = p4[2];
        int o = 4 * i;
        g_pts4[o + 0] = make_float4(a.x, a.y, a.z, 0.0f);
        g_pts4[o + 1] = make_float4(a.w, b.x, b.y, 0.0f);
        g_pts4[o + 2] = make_float4(b.z, b.w, c.x, 0.0f);
        g_pts4[o + 3] = make_float4(c.y, c.z, c.w, 0.0f);
    }

    // ---- grid barrier (all 888 CTAs are co-resident by construction) ----
    __syncthreads();                       // all block's pad stores issued
    if (tid == 0) {
        unsigned my_phase = *(volatile unsigned*)&g_bar_phase;
        __threadfence();                   // publish pad stores
        unsigned arrived = atomicAdd(&g_bar_count, 1u);
        if (arrived == GRID_MAIN - 1) {
            g_bar_count = 0u;              // reset for next replay
            __threadfence();
            atomicAdd(&g_bar_phase, 1u);   // release
        } else {
            while (*(volatile unsigned*)&g_bar_phase == my_phase) {
                __nanosleep(64);
            }
        }
        __threadfence();                   // acquire
    }
    __syncthreads();

    // ---- phase 2: gather + accumulate ----
    float tsum = 0.0f;
    for (int t = gtid; t < NTASKS; t += gstride) {
        int n = t >> 1;   // point id

        const int4* idx4 = reinterpret_cast<const int4*>(idx) + t * 2;
        int4 i0 = __ldcs(&idx4[0]);
        int4 i1 = __ldcs(&idx4[1]);

        // 8 independent 16B gathers — all outstanding simultaneously.
        float4 q0 = __ldg(&g_pts4[i0.x]);
        float4 q1 = __ldg(&g_pts4[i0.y]);
        float4 q2 = __ldg(&g_pts4[i0.z]);
        float4 q3 = __ldg(&g_pts4[i0.w]);
        float4 q4 = __ldg(&g_pts4[i1.x]);
        float4 q5 = __ldg(&g_pts4[i1.y]);
        float4 q6 = __ldg(&g_pts4[i1.z]);
        float4 q7 = __ldg(&g_pts4[i1.w]);

        const float4* orig4 = reinterpret_cast<const float4*>(orig) + t * 2;
        float4 o0 = __ldcs(&orig4[0]);
        float4 o1 = __ldcs(&orig4[1]);
        float4 p  = __ldg(&g_pts4[n]);

        float dx, dy, dz, curr, e;
        #define ACC(q, ov)                                        \
            dx = p.x - q.x; dy = p.y - q.y; dz = p.z - q.z;       \
            curr = fmaf(dx, dx, fmaf(dy, dy, dz * dz));           \
            e = curr - ov;                                        \
            tsum = fmaf(e, e, tsum);
        ACC(q0, o0.x) ACC(q1, o0.y) ACC(q2, o0.z) ACC(q3, o0.w)
        ACC(q4, o1.x) ACC(q5, o1.y) ACC(q6, o1.z) ACC(q7, o1.w)
        #undef ACC
    }

    // ---- reduce: warp -> block -> global ----
    #pragma unroll
    for (int off = 16; off > 0; off >>= 1)
        tsum += __shfl_down_sync(0xFFFFFFFFu, tsum, off);

    __shared__ float warp_sums[8];
    int lane = tid & 31;
    int wid  = tid >> 5;
    if (lane == 0) warp_sums[wid] = tsum;
    __syncthreads();
    if (wid == 0) {
        float bs = (lane < 8) ? warp_sums[lane] : 0.0f;
        #pragma unroll
        for (int off = 4; off > 0; off >>= 1)
            bs += __shfl_down_sync(0xFFFFFFFFu, bs, off);
        if (lane == 0) {
            atomicAdd(&g_acc, (double)bs);
            __threadfence();
            unsigned tk = atomicAdd(&g_ticket, 1u);
            if (tk == GRID_MAIN - 1) {
                double total = atomicAdd(&g_acc, 0.0);   // atomic read
                out[0] = (float)(total * (100000.0 / 16777216.0));
            }
        }
    }
}

extern "C" void kernel_launch(void* const* d_in, const int* in_sizes, int n_in,
                              void* d_out, int out_size) {
    const float* points = (const float*)d_in[0];
    const int*   nidx   = (const int*)d_in[1];
    const float* orig   = (const float*)d_in[2];
    float* out = (float*)d_out;

    (void)in_sizes; (void)n_in; (void)out_size;

    neighbour_loss_fused<<<GRID_MAIN, NTHREADS>>>(points, nidx, orig, out);
}

// round 6
// speedup vs baseline: 1.0088x; 1.0088x over previous
#include <cuda_runtime.h>
#include <cuda_bf16.h>

#define NPTS 1048576
#define KNEI 16
#define NTASKS (2 * NPTS)          // 2 tasks per point, 8 nbrs each
#define GRID_MAIN 888              // 148 SMs x 6 CTAs
#define NTHREADS 256

// Padded points: 16B rows -> each random gather = exactly one L1tex
// wavefront / one 32B L2 sector.
__device__ float4 g_pts4[NPTS];
__device__ double g_acc;
__device__ unsigned int g_ticket;

// Kernel 1: pad [N,3] f32 -> [N] float4 (4 points per thread) and reset
// accumulator + ticket (every graph replay). Fires the PDL trigger as soon
// as this thread's stores are issued so the dependent kernel can spin up.
__global__ void __launch_bounds__(256) pad_points_kernel(const float* __restrict__ pts) {
    int i = blockIdx.x * blockDim.x + threadIdx.x;   // 0 .. 262143
    if (i == 0) { g_acc = 0.0; g_ticket = 0u; }

    const float4* p4 = reinterpret_cast<const float4*>(pts) + 3 * i;
    float4 a = p4[0];
    float4 b = p4[1];
    float4 c = p4[2];

    int o = 4 * i;
    g_pts4[o + 0] = make_float4(a.x, a.y, a.z, 0.0f);
    g_pts4[o + 1] = make_float4(a.w, b.x, b.y, 0.0f);
    g_pts4[o + 2] = make_float4(b.z, b.w, c.x, 0.0f);
    g_pts4[o + 3] = make_float4(c.y, c.z, c.w, 0.0f);

    cudaTriggerProgrammaticLaunchCompletion();
}

// Kernel 2: persistent grid-stride over 2M pair-tasks (8 neighbours each).
// Launched with PDL: the prologue (first idx/orig loads) overlaps the pad
// kernel; cudaGridDependencySynchronize() gates only the g_pts4 gathers.
// idx/orig loads for iteration i+1 are issued under iteration i's gather
// latency (software pipeline).
__global__ void __launch_bounds__(NTHREADS, 4) neighbour_loss_kernel(
    const int* __restrict__ idx,
    const float* __restrict__ orig,
    float* __restrict__ out)
{
    const int gtid = blockIdx.x * NTHREADS + threadIdx.x;
    const int stride = GRID_MAIN * NTHREADS;

    const int4*   ip = reinterpret_cast<const int4*>(idx);
    const float4* op = reinterpret_cast<const float4*>(orig);

    // Prologue: first task's streamed loads — independent of pad output.
    int t = gtid;                       // gtid < stride <= NTASKS, always valid
    int4   i0 = ip[2 * t + 0];
    int4   i1 = ip[2 * t + 1];
    float4 o0 = op[2 * t + 0];
    float4 o1 = op[2 * t + 1];

    // Now wait for the pad kernel's results to be visible.
    cudaGridDependencySynchronize();

    float tsum = 0.0f;
    for (;;) {
        // 8 independent 16B gathers — all outstanding simultaneously.
        float4 q0 = __ldg(&g_pts4[i0.x]);
        float4 q1 = __ldg(&g_pts4[i0.y]);
        float4 q2 = __ldg(&g_pts4[i0.z]);
        float4 q3 = __ldg(&g_pts4[i0.w]);
        float4 q4 = __ldg(&g_pts4[i1.x]);
        float4 q5 = __ldg(&g_pts4[i1.y]);
        float4 q6 = __ldg(&g_pts4[i1.z]);
        float4 q7 = __ldg(&g_pts4[i1.w]);
        float4 p  = __ldg(&g_pts4[t >> 1]);

        // Prefetch next iteration's streamed data under the gather latency.
        int tn = t + stride;
        bool more = tn < NTASKS;
        int4 ni0, ni1; float4 no0, no1;
        if (more) {
            ni0 = ip[2 * tn + 0];
            ni1 = ip[2 * tn + 1];
            no0 = op[2 * tn + 0];
            no1 = op[2 * tn + 1];
        }

        float dx, dy, dz, curr, e;
        #define ACC(q, ov)                                        \
            dx = p.x - q.x; dy = p.y - q.y; dz = p.z - q.z;       \
            curr = fmaf(dx, dx, fmaf(dy, dy, dz * dz));           \
            e = curr - ov;                                        \
            tsum = fmaf(e, e, tsum);
        ACC(q0, o0.x) ACC(q1, o0.y) ACC(q2, o0.z) ACC(q3, o0.w)
        ACC(q4, o1.x) ACC(q5, o1.y) ACC(q6, o1.z) ACC(q7, o1.w)
        #undef ACC

        if (!more) break;
        t = tn;
        i0 = ni0; i1 = ni1; o0 = no0; o1 = no1;
    }

    // ---- reduce: warp -> block -> global; fused finalize ----
    #pragma unroll
    for (int off = 16; off > 0; off >>= 1)
        tsum += __shfl_down_sync(0xFFFFFFFFu, tsum, off);

    __shared__ float warp_sums[8];
    int lane = threadIdx.x & 31;
    int wid  = threadIdx.x >> 5;
    if (lane == 0) warp_sums[wid] = tsum;
    __syncthreads();
    if (wid == 0) {
        float bs = (lane < 8) ? warp_sums[lane] : 0.0f;
        #pragma unroll
        for (int off = 4; off > 0; off >>= 1)
            bs += __shfl_down_sync(0xFFFFFFFFu, bs, off);
        if (lane == 0) {
            atomicAdd(&g_acc, (double)bs);
            __threadfence();
            unsigned tk = atomicAdd(&g_ticket, 1u);
            if (tk == GRID_MAIN - 1) {
                double total = atomicAdd(&g_acc, 0.0);   // atomic read
                out[0] = (float)(total * (100000.0 / 16777216.0));
            }
        }
    }
}

extern "C" void kernel_launch(void* const* d_in, const int* in_sizes, int n_in,
                              void* d_out, int out_size) {
    const float* points = (const float*)d_in[0];
    const int*   nidx   = (const int*)d_in[1];
    const float* orig   = (const float*)d_in[2];
    float* out = (float*)d_out;

    (void)in_sizes; (void)n_in; (void)out_size;

    pad_points_kernel<<<1024, 256>>>(points);   // 4 pts/thread

    // Main kernel with Programmatic Dependent Launch: may begin executing
    // while pad_points_kernel is still running; correctness is enforced by
    // cudaGridDependencySynchronize() inside the kernel.
    cudaLaunchConfig_t cfg = {};
    cfg.gridDim  = dim3(GRID_MAIN);
    cfg.blockDim = dim3(NTHREADS);
    cfg.dynamicSmemBytes = 0;
    cfg.stream = 0;
    cudaLaunchAttribute attrs[1];
    attrs[0].id = cudaLaunchAttributeProgrammaticStreamSerialization;
    attrs[0].val.programmaticStreamSerializationAllowed = 1;
    cfg.attrs = attrs;
    cfg.numAttrs = 1;
    cudaLaunchKernelEx(&cfg, neighbour_loss_kernel, nidx, orig, out);
}

// round 7
// speedup vs baseline: 1.0916x; 1.0820x over previous
#include <cuda_runtime.h>
#include <cuda_bf16.h>

#define NPTS 1048576
#define KNEI 16
#define NTASKS (2 * NPTS)          // 2 tasks per point, 8 nbrs each
#define GRID_MAIN 888              // 148 SMs x 6 CTAs (42-reg cap via launch_bounds)
#define NTHREADS 256

// Padded points: 16B rows -> each random gather = exactly one L1tex
// wavefront / one 32B L2 sector.
__device__ float4 g_pts4[NPTS];
__device__ double g_acc;
__device__ unsigned int g_ticket;

// Kernel 1: pad [N,3] f32 -> [N] float4 (4 points per thread) and reset
// accumulator + ticket (every graph replay). PDL trigger fires once this
// block's stores are issued so the main kernel can ramp up under our tail.
__global__ void __launch_bounds__(256) pad_points_kernel(const float* __restrict__ pts) {
    int i = blockIdx.x * blockDim.x + threadIdx.x;   // 0 .. 262143
    if (i == 0) { g_acc = 0.0; g_ticket = 0u; }

    const float4* p4 = reinterpret_cast<const float4*>(pts) + 3 * i;
    float4 a = p4[0];
    float4 b = p4[1];
    float4 c = p4[2];

    int o = 4 * i;
    g_pts4[o + 0] = make_float4(a.x, a.y, a.z, 0.0f);
    g_pts4[o + 1] = make_float4(a.w, b.x, b.y, 0.0f);
    g_pts4[o + 2] = make_float4(b.z, b.w, c.x, 0.0f);
    g_pts4[o + 3] = make_float4(c.y, c.z, c.w, 0.0f);

    cudaTriggerProgrammaticLaunchCompletion();
}

// Kernel 2: persistent grid-stride over 2M pair-tasks (8 neighbours each).
// Exactly the R4 40-reg loop body; PDL sync at the top only.
__global__ void __launch_bounds__(NTHREADS, 6) neighbour_loss_kernel(
    const int* __restrict__ idx,
    const float* __restrict__ orig,
    float* __restrict__ out)
{
    // Wait for pad kernel's results (PDL overlap happens before this point).
    cudaGridDependencySynchronize();

    const int stride = GRID_MAIN * NTHREADS;
    float tsum = 0.0f;

    for (int t = blockIdx.x * NTHREADS + threadIdx.x; t < NTASKS; t += stride) {
        int n = t >> 1;   // point id

        const int4* idx4 = reinterpret_cast<const int4*>(idx) + t * 2;
        int4 i0 = idx4[0];
        int4 i1 = idx4[1];

        // 8 independent 16B gathers — all outstanding simultaneously.
        float4 q0 = __ldg(&g_pts4[i0.x]);
        float4 q1 = __ldg(&g_pts4[i0.y]);
        float4 q2 = __ldg(&g_pts4[i0.z]);
        float4 q3 = __ldg(&g_pts4[i0.w]);
        float4 q4 = __ldg(&g_pts4[i1.x]);
        float4 q5 = __ldg(&g_pts4[i1.y]);
        float4 q6 = __ldg(&g_pts4[i1.z]);
        float4 q7 = __ldg(&g_pts4[i1.w]);

        const float4* orig4 = reinterpret_cast<const float4*>(orig) + t * 2;
        float4 o0 = orig4[0];
        float4 o1 = orig4[1];
        float4 p  = g_pts4[n];

        float dx, dy, dz, curr, e;
        #define ACC(q, ov)                                        \
            dx = p.x - q.x; dy = p.y - q.y; dz = p.z - q.z;       \
            curr = fmaf(dx, dx, fmaf(dy, dy, dz * dz));           \
            e = curr - ov;                                        \
            tsum = fmaf(e, e, tsum);
        ACC(q0, o0.x) ACC(q1, o0.y) ACC(q2, o0.z) ACC(q3, o0.w)
        ACC(q4, o1.x) ACC(q5, o1.y) ACC(q6, o1.z) ACC(q7, o1.w)
        #undef ACC
    }

    // ---- reduce: warp -> block -> global; fused finalize ----
    #pragma unroll
    for (int off = 16; off > 0; off >>= 1)
        tsum += __shfl_down_sync(0xFFFFFFFFu, tsum, off);

    __shared__ float warp_sums[8];
    int lane = threadIdx.x & 31;
    int wid  = threadIdx.x >> 5;
    if (lane == 0) warp_sums[wid] = tsum;
    __syncthreads();
    if (wid == 0) {
        float bs = (lane < 8) ? warp_sums[lane] : 0.0f;
        #pragma unroll
        for (int off = 4; off > 0; off >>= 1)
            bs += __shfl_down_sync(0xFFFFFFFFu, bs, off);
        if (lane == 0) {
            atomicAdd(&g_acc, (double)bs);
            __threadfence();
            unsigned tk = atomicAdd(&g_ticket, 1u);
            if (tk == GRID_MAIN - 1) {
                double total = atomicAdd(&g_acc, 0.0);   // atomic read
                out[0] = (float)(total * (100000.0 / 16777216.0));
            }
        }
    }
}

extern "C" void kernel_launch(void* const* d_in, const int* in_sizes, int n_in,
                              void* d_out, int out_size) {
    const float* points = (const float*)d_in[0];
    const int*   nidx   = (const int*)d_in[1];
    const float* orig   = (const float*)d_in[2];
    float* out = (float*)d_out;

    (void)in_sizes; (void)n_in; (void)out_size;

    pad_points_kernel<<<1024, 256>>>(points);   // 4 pts/thread

    // Main kernel with Programmatic Dependent Launch: its launch/ramp
    // overlaps the pad kernel's tail; cudaGridDependencySynchronize()
    // inside the kernel enforces correctness.
    cudaLaunchConfig_t cfg = {};
    cfg.gridDim  = dim3(GRID_MAIN);
    cfg.blockDim = dim3(NTHREADS);
    cfg.dynamicSmemBytes = 0;
    cfg.stream = 0;
    cudaLaunchAttribute attrs[1];
    attrs[0].id = cudaLaunchAttributeProgrammaticStreamSerialization;
    attrs[0].val.programmaticStreamSerializationAllowed = 1;
    cfg.attrs = attrs;
    cfg.numAttrs = 1;
    cudaLaunchKernelEx(&cfg, neighbour_loss_kernel, nidx, orig, out);
}